// round 16
// baseline (speedup 1.0000x reference)
#include <cuda_runtime.h>
#include <cstdint>

// Problem constants (fixed by the reference):
//   NUM_BLOCKS=8192, BLOCK_SIZE=16, NUM_HEADS=8, HEAD_SIZE=128
//   NUM_TOKENS=65536, NUM_SLOTS = 8192*16 = 131072
//   per-slot payload = 8*128 fp32 = 1024 floats = 4096 bytes = 256 float4
#define NUM_SLOTS       131072
#define NUM_TOKENS      65536
#define VEC4_PER_SLOT   256
#define SLOTS_PER_BLOCK 4

// Inverse slot map, encoded token+1 (0 = slot untouched).
// INVARIANT: all-zero at entry to kernel_launch. Zero-initialized at module
// load; the merge kernel restores every entry it consumes back to zero, so
// every call sees the same initial state and does identical work.
__device__ int g_inv_map[NUM_SLOTS];

// One token per thread: one coalesced 4B load + one scattered 4B store.
__global__ void __launch_bounds__(512) scatter_inv_map_kernel(
    const int* __restrict__ slot_mapping)
{
    int i = blockIdx.x * blockDim.x + threadIdx.x;   // i in [0, NUM_TOKENS)
    g_inv_map[slot_mapping[i]] = i + 1;              // token+1 encoding
}

// One block per 4 consecutive slots; 256 threads each move float4 #t of each
// of the 4 slots. 4 independent 16B loads front-batched per thread (MLP=4),
// fully coalesced, regs ~28 -> occ ~84%. Reads: __ldcs (evict-first, zero
// reuse). Writes: __stwt (write-through) so the 512 MiB output stream does
// not occupy L2 write-allocate capacity against the read stream.
// After reading its 4 map entries (single int4 broadcast), the block restores
// them to zero (thread 0, behind a barrier) to maintain the invariant.
// Latency hiding comes from grid depth (32768 independent CTAs; R10 showed
// persistent CTAs are strictly worse for this pattern).
__global__ void __launch_bounds__(256, 8) merge_write_kernel(
    const float4* __restrict__ to_cache,
    const float4* __restrict__ kv_cache,
    float4* __restrict__ out)
{
    const unsigned slot_base = blockIdx.x * SLOTS_PER_BLOCK;
    const unsigned t = threadIdx.x;

    // All 4 map entries in one 16B broadcast load.
    const int4 m = *(const int4*)&g_inv_map[slot_base];
    const int srcs[SLOTS_PER_BLOCK] = { m.x, m.y, m.z, m.w };

    const float4* srcp[SLOTS_PER_BLOCK];
#pragma unroll
    for (int s = 0; s < SLOTS_PER_BLOCK; s++) {
        const unsigned slot = slot_base + s;
        srcp[s] = (srcs[s] > 0) ? (to_cache + (size_t)(srcs[s] - 1) * VEC4_PER_SLOT)
                                : (kv_cache + (size_t)slot * VEC4_PER_SLOT);
    }

    // Front-batch the 4 independent payload loads (in flight across the barrier).
    float4 v[SLOTS_PER_BLOCK];
#pragma unroll
    for (int s = 0; s < SLOTS_PER_BLOCK; s++)
        v[s] = __ldcs(srcp[s] + t);

    // All warps have read the map entries; now it is safe to clear them.
    __syncthreads();
    if (t == 0)
        *(int4*)&g_inv_map[slot_base] = make_int4(0, 0, 0, 0);

#pragma unroll
    for (int s = 0; s < SLOTS_PER_BLOCK; s++)
        __stwt(out + (size_t)(slot_base + s) * VEC4_PER_SLOT + t, v[s]);
}

extern "C" void kernel_launch(void* const* d_in, const int* in_sizes, int n_in,
                              void* d_out, int out_size)
{
    const float4* to_cache     = (const float4*)d_in[0];  // [65536, 8, 128] f32
    const float4* kv_cache     = (const float4*)d_in[1];  // [8192, 16, 8, 128] f32
    const int*    slot_mapping = (const int*)d_in[2];     // [65536] i32
    float4*       out          = (float4*)d_out;          // full updated kv_cache

    scatter_inv_map_kernel<<<NUM_TOKENS / 512, 512>>>(slot_mapping);
    merge_write_kernel<<<NUM_SLOTS / SLOTS_PER_BLOCK, 256>>>(to_cache, kv_cache, out);
}

// round 17
// speedup vs baseline: 1.0150x; 1.0150x over previous
#include <cuda_runtime.h>
#include <cstdint>

// ── FINAL (champion, reproduced at 161.9 us across R6/R12/R14) ──
//
// basic_cache scatter-write, reformulated as a single merged streaming pass:
//   1) scatter_inv_map: inv_map[slot] = token+1 (0 = untouched). 65536
//      coalesced 4B loads + scattered 4B stores.
//   2) merge_write: one pass over all 131072 slots; each output slot's 4 KiB
//      is read exactly once from either to_cache (if a token targets it) or
//      kv_cache, and written once. Total traffic = 512 MiB R + 512 MiB W +
//      ~1.3 MiB map = the information-theoretic minimum.
// Measured: merge @ ~6.65 TB/s (84% DRAM spec) — the practical streaming
// ceiling for this mixed gathered-read/sequential-write pattern on sm_103a.
//
// Session findings baked in:
//   - MLP=4 @ occ 84% saturates; MLP=8 lowered occupancy and DRAM% (R4).
//   - 32768 independent CTAs beat a persistent grid + SW barrier (R10):
//     grid depth is the latency-hiding mechanism for pure streaming.
//   - PDL overlap of the two kernels: neutral (R8).
//   - __stcs on both streams; __stwt write-through regressed ~2.5 us (R16).
//   - Self-cleaning inv_map removes the memset node: the map is zero-init at
//     module load and every merge block restores its 4 entries to zero, so
//     each call sees identical initial state (deterministic, no caching).

#define NUM_SLOTS       131072
#define NUM_TOKENS      65536
#define VEC4_PER_SLOT   256
#define SLOTS_PER_BLOCK 4

// Inverse slot map, encoded token+1 (0 = slot untouched).
// INVARIANT: all-zero at entry to kernel_launch (see header note).
__device__ int g_inv_map[NUM_SLOTS];

// One token per thread: one coalesced 4B load + one scattered 4B store.
__global__ void __launch_bounds__(512) scatter_inv_map_kernel(
    const int* __restrict__ slot_mapping)
{
    int i = blockIdx.x * blockDim.x + threadIdx.x;   // i in [0, NUM_TOKENS)
    g_inv_map[slot_mapping[i]] = i + 1;              // token+1 encoding
}

// One block per 4 consecutive slots; 256 threads each move float4 #t of each
// of the 4 slots. 4 independent 16B loads front-batched per thread (MLP=4),
// fully coalesced, regs ~28 -> occ ~84%. Streaming hints: zero reuse.
// After reading its 4 map entries (single int4 broadcast), the block restores
// them to zero (thread 0, behind a barrier) to maintain the invariant.
__global__ void __launch_bounds__(256, 8) merge_write_kernel(
    const float4* __restrict__ to_cache,
    const float4* __restrict__ kv_cache,
    float4* __restrict__ out)
{
    const unsigned slot_base = blockIdx.x * SLOTS_PER_BLOCK;
    const unsigned t = threadIdx.x;

    // All 4 map entries in one 16B broadcast load.
    const int4 m = *(const int4*)&g_inv_map[slot_base];
    const int srcs[SLOTS_PER_BLOCK] = { m.x, m.y, m.z, m.w };

    const float4* srcp[SLOTS_PER_BLOCK];
#pragma unroll
    for (int s = 0; s < SLOTS_PER_BLOCK; s++) {
        const unsigned slot = slot_base + s;
        srcp[s] = (srcs[s] > 0) ? (to_cache + (size_t)(srcs[s] - 1) * VEC4_PER_SLOT)
                                : (kv_cache + (size_t)slot * VEC4_PER_SLOT);
    }

    // Front-batch the 4 independent payload loads (in flight across the barrier).
    float4 v[SLOTS_PER_BLOCK];
#pragma unroll
    for (int s = 0; s < SLOTS_PER_BLOCK; s++)
        v[s] = __ldcs(srcp[s] + t);

    // All warps have read the map entries; now it is safe to clear them.
    __syncthreads();
    if (t == 0)
        *(int4*)&g_inv_map[slot_base] = make_int4(0, 0, 0, 0);

#pragma unroll
    for (int s = 0; s < SLOTS_PER_BLOCK; s++)
        __stcs(out + (size_t)(slot_base + s) * VEC4_PER_SLOT + t, v[s]);
}

extern "C" void kernel_launch(void* const* d_in, const int* in_sizes, int n_in,
                              void* d_out, int out_size)
{
    const float4* to_cache     = (const float4*)d_in[0];  // [65536, 8, 128] f32
    const float4* kv_cache     = (const float4*)d_in[1];  // [8192, 16, 8, 128] f32
    const int*    slot_mapping = (const int*)d_in[2];     // [65536] i32
    float4*       out          = (float4*)d_out;          // full updated kv_cache

    scatter_inv_map_kernel<<<NUM_TOKENS / 512, 512>>>(slot_mapping);
    merge_write_kernel<<<NUM_SLOTS / SLOTS_PER_BLOCK, 256>>>(to_cache, kv_cache, out);
}